// round 1
// baseline (speedup 1.0000x reference)
#include <cuda_runtime.h>
#include <cuda_bf16.h>
#include <cstdint>

#define IMG   4096
#define OUT   4097
#define TX    128
#define TY    32
#define XP    (TX + 5)   // 133  x-tile pitch
#define XR    (TY + 5)   // 37   x-tile rows
#define HP    (TX + 3)   // 131  hist-tile pitch
#define HR    (TY + 3)   // 35   hist-tile rows
#define OPLANE (OUT * OUT)  // 16785409

// orientation basis: theta_o = (2o+1) * pi/8
__device__ __constant__ float COSA[8] = {
     0.9238795325112867f,  0.3826834323650898f, -0.3826834323650898f, -0.9238795325112867f,
    -0.9238795325112867f, -0.3826834323650898f,  0.3826834323650898f,  0.9238795325112867f };
__device__ __constant__ float SINA[8] = {
     0.3826834323650898f,  0.9238795325112867f,  0.9238795325112867f,  0.3826834323650898f,
    -0.3826834323650898f, -0.9238795325112867f, -0.9238795325112867f, -0.3826834323650898f };

__device__ __forceinline__ void accum_row(const unsigned* __restrict__ p, float rs[8]) {
#pragma unroll
    for (int j = 0; j < 4; ++j) {
        unsigned h  = p[j];
        float mag   = __uint_as_float(h & 0xFFFFFFF8u);
        int   idx   = (int)(h & 7u);
#pragma unroll
        for (int c = 0; c < 8; ++c)
            rs[c] += (idx == c) ? mag : 0.0f;
    }
}

__global__ __launch_bounds__(256)
void sift_fused_kernel(const float* __restrict__ x, float* __restrict__ out)
{
    __shared__ float    xs[XR * XP];
    __shared__ unsigned hs[HR * HP];

    const int tid = threadIdx.x;
    const int ox0 = blockIdx.x * TX;
    const int oy0 = blockIdx.y * TY;

    // ---- phase 1: load x tile (rows oy0-3 .. oy0+TY+1, cols ox0-3 .. ox0+TX+1), zero-padded
    for (int e = tid; e < XR * XP; e += 256) {
        int r  = e / XP;
        int c  = e - r * XP;
        int gy = oy0 - 3 + r;
        int gx = ox0 - 3 + c;
        float v = 0.0f;
        if ((unsigned)gy < (unsigned)IMG && (unsigned)gx < (unsigned)IMG)
            v = x[gy * IMG + gx];
        xs[e] = v;
    }
    __syncthreads();

    // ---- phase 2: sobel -> orientation argmax -> packed (mag | idx) hist tile
    for (int e = tid; e < HR * HP; e += 256) {
        int hy = e / HP;
        int hx = e - hy * HP;
        int gy = oy0 - 2 + hy;
        int gx = ox0 - 2 + hx;
        unsigned pv = 0u;
        if ((unsigned)gy < (unsigned)IMG && (unsigned)gx < (unsigned)IMG) {
            const float* p = xs + hy * XP + hx;   // top-left of 3x3
            float a00 = p[0],        a01 = p[1],        a02 = p[2];
            float a10 = p[XP],       a12 = p[XP + 2];
            float a20 = p[2 * XP],   a21 = p[2 * XP + 1], a22 = p[2 * XP + 2];
            float dx = (a02 + 2.0f * a12 + a22) - (a00 + 2.0f * a10 + a20);
            float dy = (a20 + 2.0f * a21 + a22) - (a00 + 2.0f * a01 + a02);
            float mag = sqrtf(dx * dx + dy * dy);
            float best = COSA[0] * dx + SINA[0] * dy;
            int bi = 0;
#pragma unroll
            for (int o = 1; o < 8; ++o) {
                float co = COSA[o] * dx + SINA[o] * dy;
                if (co > best) { best = co; bi = o; }   // strict > : first-occurrence argmax
            }
            pv = (__float_as_uint(mag) & 0xFFFFFFF8u) | (unsigned)bi;
        }
        hs[e] = pv;
    }
    __syncthreads();

    // ---- phase 3: 4x4 box sum, vertical sliding window, 8 channels in registers
    const int tx   = tid & (TX - 1);
    const int q    = tid >> 7;              // 0 or 1 -> half of the tile in y
    const int ox   = ox0 + tx;
    const int oy_s = oy0 + q * (TY / 2);
    const bool oxok = (ox < OUT);
    const unsigned* hb = hs + tx;           // hist col base; window cols = tx..tx+3
    const int hy0 = q * (TY / 2);           // first window row for this thread

    float row[4][8];
    float acc[8];
#pragma unroll
    for (int c = 0; c < 8; ++c) acc[c] = 0.0f;
#pragma unroll
    for (int k = 0; k < 4; ++k) {
#pragma unroll
        for (int c = 0; c < 8; ++c) row[k][c] = 0.0f;
        accum_row(hb + (hy0 + k) * HP, row[k]);
#pragma unroll
        for (int c = 0; c < 8; ++c) acc[c] += row[k][c];
    }

#pragma unroll
    for (int i = 0; i < TY / 2; ++i) {
        int oy = oy_s + i;
        if (oxok && oy < OUT) {
            int base = oy * OUT + ox;
#pragma unroll
            for (int c = 0; c < 8; ++c)
                out[c * OPLANE + base] = acc[c];
        }
        if (i < TY / 2 - 1) {
            float nr[8];
#pragma unroll
            for (int c = 0; c < 8; ++c) nr[c] = 0.0f;
            accum_row(hb + (hy0 + 4 + i) * HP, nr);
            const int k = i & 3;
#pragma unroll
            for (int c = 0; c < 8; ++c) {
                acc[c] += nr[c] - row[k][c];
                row[k][c] = nr[c];
            }
        }
    }
}

extern "C" void kernel_launch(void* const* d_in, const int* in_sizes, int n_in,
                              void* d_out, int out_size)
{
    (void)in_sizes; (void)n_in; (void)out_size;
    const float* x = (const float*)d_in[0];
    float* out = (float*)d_out;
    dim3 grid((OUT + TX - 1) / TX, (OUT + TY - 1) / TY);  // 33 x 129
    sift_fused_kernel<<<grid, 256>>>(x, out);
}

// round 2
// speedup vs baseline: 1.0661x; 1.0661x over previous
#include <cuda_runtime.h>
#include <cuda_bf16.h>
#include <cstdint>

#define IMG   4096
#define OUT   4097
#define TX    128
#define TY    32
#define XP    (TX + 5)   // 133  x-tile pitch (floats)
#define XR    (TY + 5)   // 37   x-tile rows
#define HP    (TX + 3)   // 131  hist-tile pitch (u64)
#define HR    (TY + 3)   // 35   hist-tile rows
#define OPLANE (OUT * OUT)

#define XS_BYTES  ((XR * XP * 4 + 7) & ~7)        // pad to 8B for u64 section
#define SMEM_BYTES (XS_BYTES + HR * HP * 8)       // ~56.4 KB

typedef unsigned long long u64;
typedef unsigned int       u32;

// predicated packed add: if (pm == P) acc += v  (two fp32 lanes at once)
#define PRED_ADD2(acc, pm, P, v)                                              \
    asm("{ .reg .pred p; setp.eq.u32 p, %1, %2; @p add.rn.f32x2 %0, %0, %3; }" \
        : "+l"(acc) : "r"(pm), "n"(P), "l"(v))

#define ADD2(d, a, b)                                                         \
    asm("add.rn.f32x2 %0, %1, %2;" : "=l"(d) : "l"(a), "l"(b))

#define FMA2(d, a, b, c)                                                      \
    asm("fma.rn.f32x2 %0, %1, %2, %3;" : "=l"(d) : "l"(a), "l"(b), "l"(c))

static __device__ __forceinline__ void accum_row(const u64* __restrict__ p, u64 rs[4]) {
#pragma unroll
    for (int j = 0; j < 4; ++j) {
        u64 h  = p[j];
        u32 pm = (u32)h & 3u;           // pair index lives in low 2 bits of lo lane
        PRED_ADD2(rs[0], pm, 0, h);
        PRED_ADD2(rs[1], pm, 1, h);
        PRED_ADD2(rs[2], pm, 2, h);
        PRED_ADD2(rs[3], pm, 3, h);
    }
}

__global__ __launch_bounds__(256)
void sift_fused2_kernel(const float* __restrict__ x, float* __restrict__ out)
{
    extern __shared__ char smem[];
    float* xs = (float*)smem;
    u64*   hs = (u64*)(smem + XS_BYTES);

    const int tid = threadIdx.x;
    const int ox0 = blockIdx.x * TX;
    const int oy0 = blockIdx.y * TY;

    // ---- phase 1: load x tile, zero-padded halo
    for (int e = tid; e < XR * XP; e += 256) {
        int r  = e / XP;
        int c  = e - r * XP;
        int gy = oy0 - 3 + r;
        int gx = ox0 - 3 + c;
        float v = 0.0f;
        if ((unsigned)gy < (unsigned)IMG && (unsigned)gx < (unsigned)IMG)
            v = x[gy * IMG + gx];
        xs[e] = v;
    }
    __syncthreads();

    // ---- phase 2: sobel -> octant argmax -> pre-routed packed pair {even,odd}
    for (int e = tid; e < HR * HP; e += 256) {
        int hy = e / HP;
        int hx = e - hy * HP;
        int gy = oy0 - 2 + hy;
        int gx = ox0 - 2 + hx;
        u64 pv = 0ull;
        if ((unsigned)gy < (unsigned)IMG && (unsigned)gx < (unsigned)IMG) {
            const float* p = xs + hy * XP + hx;   // top-left of 3x3
            float a00 = p[0],      a01 = p[1],          a02 = p[2];
            float a10 = p[XP],     a12 = p[XP + 2];
            float a20 = p[2 * XP], a21 = p[2 * XP + 1], a22 = p[2 * XP + 2];
            float dx = (a02 + 2.0f * a12 + a22) - (a00 + 2.0f * a10 + a20);
            float dy = (a20 + 2.0f * a21 + a22) - (a00 + 2.0f * a01 + a02);
            float mag = sqrtf(dx * dx + dy * dy);
            // octant of atan2(dy,dx) with boundaries at k*45deg; tie rules match
            // strict-> first-occurrence argmax of the 8 cosine projections.
            int   q3  = (dy < 0.0f) ? 4 : 0;
            float dx1 = q3 ? -dx : dx;
            float dy1 = q3 ? -dy : dy;
            int   q2  = (dx1 < 0.0f) ? 2 : 0;
            float dx2 = q2 ? dy1  : dx1;
            float dy2 = q2 ? -dx1 : dy1;
            int   q1  = (dy2 > dx2) ? 1 : 0;
            int   idx = q3 + q2 + q1;
            u32 magb = __float_as_uint(mag) & 0xFFFFFFFCu;
            u32 pm   = (u32)(idx >> 1);
            u32 lo, hi;
            if (idx & 1) { lo = pm;        hi = magb; }
            else         { lo = magb | pm; hi = 0u;   }
            pv = ((u64)hi << 32) | lo;
        }
        hs[e] = pv;
    }
    __syncthreads();

    // ---- phase 3: 4x4 box sum, vertical sliding window, 4 packed-pair channels
    const int tx   = tid & (TX - 1);
    const int q    = tid >> 7;              // 0/1 -> tile half in y
    const int ox   = ox0 + tx;
    const int oy_s = oy0 + q * (TY / 2);
    const bool oxok = (ox < OUT);
    const u64* hb = hs + tx;
    const int hy0 = q * (TY / 2);

    const u64 NEG1 = 0xBF800000BF800000ull;  // {-1.0f, -1.0f}

    u64 row[4][4];
    u64 acc[4];
#pragma unroll
    for (int pp = 0; pp < 4; ++pp) acc[pp] = 0ull;
#pragma unroll
    for (int k = 0; k < 4; ++k) {
#pragma unroll
        for (int pp = 0; pp < 4; ++pp) row[k][pp] = 0ull;
        accum_row(hb + (hy0 + k) * HP, row[k]);
#pragma unroll
        for (int pp = 0; pp < 4; ++pp) ADD2(acc[pp], acc[pp], row[k][pp]);
    }

#pragma unroll 4
    for (int i = 0; i < TY / 2; ++i) {
        int oy = oy_s + i;
        if (oxok && oy < OUT) {
            int base = oy * OUT + ox;
#pragma unroll
            for (int pp = 0; pp < 4; ++pp) {
                u32 lo = (u32)acc[pp];
                u32 hi = (u32)(acc[pp] >> 32);
                out[(2 * pp)     * OPLANE + base] = __uint_as_float(lo);
                out[(2 * pp + 1) * OPLANE + base] = __uint_as_float(hi);
            }
        }
        if (i < TY / 2 - 1) {
            u64 nr[4];
#pragma unroll
            for (int pp = 0; pp < 4; ++pp) nr[pp] = 0ull;
            accum_row(hb + (hy0 + 4 + i) * HP, nr);
            const int k = i & 3;
#pragma unroll
            for (int pp = 0; pp < 4; ++pp) {
                u64 t;
                ADD2(t, acc[pp], nr[pp]);        // acc + new
                FMA2(acc[pp], row[k][pp], NEG1, t); // - old
                row[k][pp] = nr[pp];
            }
        }
    }
}

extern "C" void kernel_launch(void* const* d_in, const int* in_sizes, int n_in,
                              void* d_out, int out_size)
{
    (void)in_sizes; (void)n_in; (void)out_size;
    const float* x = (const float*)d_in[0];
    float* out = (float*)d_out;
    cudaFuncSetAttribute(sift_fused2_kernel,
                         cudaFuncAttributeMaxDynamicSharedMemorySize, SMEM_BYTES);
    dim3 grid((OUT + TX - 1) / TX, (OUT + TY - 1) / TY);  // 33 x 129
    sift_fused2_kernel<<<grid, 256, SMEM_BYTES>>>(x, out);
}